// round 16
// baseline (speedup 1.0000x reference)
#include <cuda_runtime.h>
#include <cuda_fp16.h>
#include <math.h>
#include <stdint.h>

#define NB 4
#define NC 256
#define NT 4096

typedef __half h16;

__device__ h16   g_xnhi[NB * NT * NC];
__device__ h16   g_xnlo[NB * NT * NC];
__device__ h16   g_qhi [NB * NT * NC];
__device__ h16   g_khi [NB * NT * NC];
__device__ h16   g_vThi[NC * NB * NT];
__device__ h16   g_s16 [(size_t)NB * NT * NT];
__device__ h16   g_ahi [(size_t)NB * NT * NT];
__device__ h16   g_wqhi[NC * NC];
__device__ h16   g_wkhi[NC * NC];
__device__ h16   g_wvhi[NC * NC];

__device__ __forceinline__ uint32_t smem_u32(const void* p) {
    uint32_t a;
    asm("{ .reg .u64 t; cvta.to.shared.u64 t, %1; cvt.u32.u64 %0, t; }" : "=r"(a) : "l"(p));
    return a;
}
__device__ __forceinline__ void cp16(uint32_t s, const void* g) {
    asm volatile("cp.async.cg.shared.global [%0], [%1], 16;" :: "r"(s), "l"(g));
}
__device__ __forceinline__ void cp_commit() { asm volatile("cp.async.commit_group;" ::: "memory"); }
template <int N> __device__ __forceinline__ void cp_wait() {
    asm volatile("cp.async.wait_group %0;" :: "n"(N) : "memory");
}
__device__ __forceinline__ void ldm_x4(uint32_t* r, uint32_t addr) {
    asm volatile("ldmatrix.sync.aligned.m8n8.x4.shared.b16 {%0,%1,%2,%3}, [%4];"
                 : "=r"(r[0]), "=r"(r[1]), "=r"(r[2]), "=r"(r[3]) : "r"(addr));
}
__device__ __forceinline__ void mma16816(float* d, const uint32_t* a, const uint32_t* b) {
    asm volatile(
        "mma.sync.aligned.m16n8k16.row.col.f32.f16.f16.f32 "
        "{%0,%1,%2,%3}, {%4,%5,%6,%7}, {%8,%9}, {%0,%1,%2,%3};"
        : "+f"(d[0]), "+f"(d[1]), "+f"(d[2]), "+f"(d[3])
        : "r"(a[0]), "r"(a[1]), "r"(a[2]), "r"(a[3]), "r"(b[0]), "r"(b[1]));
}
__device__ __forceinline__ uint32_t swz(uint32_t off) { return off ^ ((off >> 3) & 0x70); }
__device__ __forceinline__ uint32_t pack2h(float a, float b) {
    return (uint32_t)__half_as_ushort(__float2half_rn(a))
         | ((uint32_t)__half_as_ushort(__float2half_rn(b)) << 16);
}

// ============================================================
// pure-fp16 big-tile GEMM. warp tile 64x64, 8 warps (BM/64 x BN/64).
// BK=64, 2-stage cp.async, 1 CTA/SM.
// EPI=1: fp16 out.  EPI=2: residual(Rhi+Rlo) + transpose -> fp32 out[b,c,n].
// ============================================================
template <int BM, int BN, int EPI>
__global__ void __launch_bounds__(256, 1) gemm_big(
    const h16* __restrict__ A, long ldA, long strideA,
    const h16* __restrict__ B, long ldB, long strideB,
    h16* __restrict__ C, long ldC, long strideC, int K,
    const h16* __restrict__ Rhi, const h16* __restrict__ Rlo,
    float* __restrict__ out)
{
    extern __shared__ char dyn[];
    const uint32_t sbase = smem_u32(dyn);
    const int tid = threadIdx.x;
    const int wid = tid >> 5, lane = tid & 31;
    constexpr int WM = BM / 64;
    const int warpM = wid % WM, warpN = wid / WM;

    constexpr uint32_t APLANE = (uint32_t)BM * 128;
    constexpr uint32_t STAGE  = (uint32_t)(BM + BN) * 128;   // 48 KB
    constexpr int NCHUNK = (BM + BN) * 8 / 256;              // cp16 per thread

    const int z = blockIdx.z;
    const long m0 = (long)blockIdx.y * BM;
    const long n0 = (long)blockIdx.x * BN;
    const h16* pA = A + (size_t)z * strideA + (size_t)m0 * ldA;
    const h16* pB = B + (size_t)z * strideB + (size_t)n0 * ldB;

    const int nk = K / 64;

    auto load_stage = [&](int st, int ks) {
        uint32_t base = sbase + (uint32_t)st * STAGE;
#pragma unroll
        for (int i = 0; i < NCHUNK; i++) {
            int cid = tid + i * 256;
            if (cid < BM * 8) {
                int m = cid >> 3, c = cid & 7;
                uint32_t off = swz((uint32_t)(m * 128 + c * 16));
                cp16(base + off, pA + (size_t)m * ldA + ks * 64 + c * 8);
            } else {
                int b = cid - BM * 8;
                int m = b >> 3, c = b & 7;
                uint32_t off = swz((uint32_t)(m * 128 + c * 16));
                cp16(base + APLANE + off, pB + (size_t)m * ldB + ks * 64 + c * 8);
            }
        }
    };

    const int lr = lane & 7, lg = lane >> 3;
    float acc[4][8][4] = {};
    load_stage(0, 0); cp_commit();

    for (int ks = 0; ks < nk; ks++) {
        cp_wait<0>();
        __syncthreads();
        if (ks + 1 < nk) { load_stage((ks + 1) & 1, ks + 1); cp_commit(); }

        uint32_t aBase = sbase + (uint32_t)(ks & 1) * STAGE;
        uint32_t bBase = aBase + APLANE;

#pragma unroll
        for (int kst = 0; kst < 4; kst++) {
            const uint32_t kb = kst * 32;
            uint32_t ah[4][4], bh[8][2];
#pragma unroll
            for (int mf = 0; mf < 4; mf++) {
                uint32_t row = warpM * 64 + mf * 16 + lr + ((lg & 1) << 3);
                ldm_x4(ah[mf], aBase + swz(row * 128 + kb + ((lg >> 1) << 4)));
            }
#pragma unroll
            for (int p = 0; p < 4; p++) {
                uint32_t row = warpN * 64 + p * 16 + lr + ((lg >> 1) << 3);
                uint32_t t[4];
                ldm_x4(t, bBase + swz(row * 128 + kb + ((lg & 1) << 4)));
                bh[2*p][0] = t[0]; bh[2*p][1] = t[1];
                bh[2*p+1][0] = t[2]; bh[2*p+1][1] = t[3];
            }
#pragma unroll
            for (int mf = 0; mf < 4; mf++)
#pragma unroll
                for (int nf = 0; nf < 8; nf++)
                    mma16816(acc[mf][nf], ah[mf], bh[nf]);
        }
    }

    const int qr = lane >> 2, qc = (lane & 3) * 2;

    if (EPI == 1) {
#pragma unroll
        for (int mf = 0; mf < 4; mf++)
#pragma unroll
            for (int nf = 0; nf < 8; nf++) {
                long r0  = m0 + warpM * 64 + mf * 16 + qr;
                long col = n0 + warpN * 64 + nf * 8 + qc;
#pragma unroll
                for (int h = 0; h < 2; h++) {
                    size_t idx = (size_t)z * strideC + (size_t)(r0 + h * 8) * ldC + col;
                    *(uint32_t*)(C + idx) = pack2h(acc[mf][nf][2*h], acc[mf][nf][2*h+1]);
                }
            }
    } else {
        // EPI==2 (BM=128, BN=256): residual + transpose -> out[b,c, m0+row]
        __syncthreads();
        float* tr = (float*)dyn;                 // [256][132]
#pragma unroll
        for (int mf = 0; mf < 4; mf++)
#pragma unroll
            for (int nf = 0; nf < 8; nf++) {
                int row_l = warpM * 64 + mf * 16 + qr;
                int col_l = warpN * 64 + nf * 8 + qc;
#pragma unroll
                for (int h = 0; h < 2; h++) {
                    size_t idx = ((size_t)z * NT + m0 + row_l + h * 8) * NC + col_l;
                    uint32_t xh = *(const uint32_t*)(Rhi + idx);
                    uint32_t xl = *(const uint32_t*)(Rlo + idx);
                    float r0v = __half2float(__ushort_as_half((unsigned short)(xh & 0xffff)))
                              + __half2float(__ushort_as_half((unsigned short)(xl & 0xffff)));
                    float r1v = __half2float(__ushort_as_half((unsigned short)(xh >> 16)))
                              + __half2float(__ushort_as_half((unsigned short)(xl >> 16)));
                    tr[(col_l)     * 132 + row_l + h * 8] = acc[mf][nf][2*h]     + r0v;
                    tr[(col_l + 1) * 132 + row_l + h * 8] = acc[mf][nf][2*h + 1] + r1v;
                }
            }
        __syncthreads();
#pragma unroll
        for (int it = 0; it < 32; it++) {
            int col = (tid >> 5) + it * 8;
            int t4  = lane * 4;
            float4 v = *(float4*)&tr[col * 132 + t4];
            *(float4*)(out + ((size_t)z * NC + col) * NT + m0 + t4) = v;
        }
    }
}

// ============================================================
__global__ void __launch_bounds__(256) ln_kernel(
    const float* __restrict__ x, const float* __restrict__ gamma,
    const float* __restrict__ beta, h16* __restrict__ xnhi, h16* __restrict__ xnlo)
{
    __shared__ float sx[32][NC + 1];
    __shared__ float psum[8][33], psq[8][33];
    __shared__ float smu[32], srs[32];
    int b = blockIdx.y, n0 = blockIdx.x * 32;
    const float* xb = x + (size_t)b * NC * NT;

    for (int i = threadIdx.x; i < NC * 32; i += 256) {
        int c = i >> 5, t = i & 31;
        sx[t][c] = xb[(size_t)c * NT + n0 + t];
    }
    __syncthreads();
    int t = threadIdx.x & 31, g = threadIdx.x >> 5;
    float s0 = 0.f, s1 = 0.f;
#pragma unroll
    for (int j = 0; j < 32; j++) { float v = sx[t][g * 32 + j]; s0 += v; s1 += v * v; }
    psum[g][t] = s0; psq[g][t] = s1;
    __syncthreads();
    if (threadIdx.x < 32) {
        float a = 0.f, bb = 0.f;
#pragma unroll
        for (int j = 0; j < 8; j++) { a += psum[j][threadIdx.x]; bb += psq[j][threadIdx.x]; }
        float mu = a * (1.0f / NC);
        smu[threadIdx.x] = mu;
        srs[threadIdx.x] = rsqrtf(bb * (1.0f / NC) - mu * mu + 1e-5f);
    }
    __syncthreads();
    size_t base = ((size_t)b * NT + n0) * NC;
    for (int i = threadIdx.x; i < NC * 32; i += 256) {
        int tok = i >> 8, c = i & 255;
        float r = (sx[tok][c] - smu[tok]) * srs[tok] * gamma[c] + beta[c];
        float h = __half2float(__float2half_rn(r));
        xnhi[base + (size_t)tok * NC + c] = __float2half_rn(r);
        xnlo[base + (size_t)tok * NC + c] = __float2half_rn(r - h);
    }
}

__global__ void prep_kernel(
    const float* __restrict__ Wq, const float* __restrict__ Wk, const float* __restrict__ Wv,
    h16* qh, h16* kh, h16* vh)
{
    int n = blockIdx.x, k = threadIdx.x;
    size_t src = (size_t)k * NC + n, dst = (size_t)n * NC + k;
    qh[dst] = __float2half_rn(Wq[src]);
    kh[dst] = __float2half_rn(Wk[src]);
    vh[dst] = __float2half_rn(Wv[src]);
}

// mix: attn = a1*softmax + a2*relu^2, fp16 in/out
__global__ void __launch_bounds__(256) mix_kernel(
    const float* __restrict__ w1, const float* __restrict__ w2,
    const h16* __restrict__ S, h16* __restrict__ ahi)
{
    size_t ro = ((size_t)blockIdx.y * NT + blockIdx.x) * NT;
    const uint2* row2 = (const uint2*)(S + ro);
    int tid = threadIdx.x;
    __shared__ float sred[8];

    float v[16];
    float mx = -1e30f;
#pragma unroll
    for (int g = 0; g < 4; g++) {
        uint2 u = row2[g * 256 + tid];
        v[g*4+0] = __half2float(__ushort_as_half((unsigned short)(u.x & 0xffff)));
        v[g*4+1] = __half2float(__ushort_as_half((unsigned short)(u.x >> 16)));
        v[g*4+2] = __half2float(__ushort_as_half((unsigned short)(u.y & 0xffff)));
        v[g*4+3] = __half2float(__ushort_as_half((unsigned short)(u.y >> 16)));
    }
#pragma unroll
    for (int i = 0; i < 16; i++) mx = fmaxf(mx, v[i]);
#pragma unroll
    for (int o = 16; o; o >>= 1) mx = fmaxf(mx, __shfl_xor_sync(0xffffffffu, mx, o));
    if ((tid & 31) == 0) sred[tid >> 5] = mx;
    __syncthreads();
    mx = sred[0];
#pragma unroll
    for (int i = 1; i < 8; i++) mx = fmaxf(mx, sred[i]);
    __syncthreads();

    float e[16];
    float sum = 0.f;
#pragma unroll
    for (int i = 0; i < 16; i++) { e[i] = __expf(v[i] - mx); sum += e[i]; }
#pragma unroll
    for (int o = 16; o; o >>= 1) sum += __shfl_xor_sync(0xffffffffu, sum, o);
    if ((tid & 31) == 0) sred[tid >> 5] = sum;
    __syncthreads();
    sum = 0.f;
#pragma unroll
    for (int i = 0; i < 8; i++) sum += sred[i];

    float e1 = __expf(w1[0]), e2 = __expf(w2[0]);
    float a1 = e1 / (e1 + e2), a2 = e2 / (e1 + e2);
    float inv = a1 / sum;

    uint2* oh = (uint2*)(ahi + ro);
#pragma unroll
    for (int g = 0; g < 4; g++) {
        float p[4];
#pragma unroll
        for (int j = 0; j < 4; j++) {
            float r = fmaxf(v[g*4+j], 0.f);
            p[j] = e[g*4+j] * inv + a2 * r * r;
        }
        oh[g * 256 + tid] = make_uint2(pack2h(p[0], p[1]), pack2h(p[2], p[3]));
    }
}

// ============================================================
extern "C" void kernel_launch(void* const* d_in, const int* in_sizes, int n_in,
                              void* d_out, int out_size)
{
    const float* x     = (const float*)d_in[0];
    const float* gamma = (const float*)d_in[1];
    const float* beta  = (const float*)d_in[2];
    const float* Wq    = (const float*)d_in[3];
    const float* Wk    = (const float*)d_in[4];
    const float* Wv    = (const float*)d_in[5];
    const float* w1    = (const float*)d_in[6];
    const float* w2    = (const float*)d_in[7];
    float* out = (float*)d_out;

    h16 *xnhi, *xnlo, *qhi, *khi, *vThi, *wqhi, *wkhi, *wvhi, *ahi, *s16;
    cudaGetSymbolAddress((void**)&xnhi, g_xnhi); cudaGetSymbolAddress((void**)&xnlo, g_xnlo);
    cudaGetSymbolAddress((void**)&qhi,  g_qhi);
    cudaGetSymbolAddress((void**)&khi,  g_khi);
    cudaGetSymbolAddress((void**)&vThi, g_vThi);
    cudaGetSymbolAddress((void**)&wqhi, g_wqhi);
    cudaGetSymbolAddress((void**)&wkhi, g_wkhi);
    cudaGetSymbolAddress((void**)&wvhi, g_wvhi);
    cudaGetSymbolAddress((void**)&ahi,  g_ahi);  cudaGetSymbolAddress((void**)&s16,  g_s16);

    const int SM_S = 2 * (256 + 128) * 128;          // 96 KB
    const int SM_O = 256 * 132 * 4;                  // 135168 B (> pipeline 96 KB)
    cudaFuncSetAttribute((const void*)gemm_big<256,128,1>, cudaFuncAttributeMaxDynamicSharedMemorySize, SM_S);
    cudaFuncSetAttribute((const void*)gemm_big<128,256,2>, cudaFuncAttributeMaxDynamicSharedMemorySize, SM_O);

    // 1) LayerNorm -> xn pair
    ln_kernel<<<dim3(NT / 32, NB), 256>>>(x, gamma, beta, xnhi, xnlo);
    // 2) weight transpose
    prep_kernel<<<NC, NC>>>(Wq, Wk, Wv, wqhi, wkhi, wvhi);
    // 3-5) Q, K, V^T projections (pure fp16, big tile)
    gemm_big<256,128,1><<<dim3(2, 64, 1), 256, SM_S>>>(
        xnhi, NC, 0, wqhi, NC, 0, qhi, NC, 0, NC, nullptr, nullptr, nullptr);
    gemm_big<256,128,1><<<dim3(2, 64, 1), 256, SM_S>>>(
        xnhi, NC, 0, wkhi, NC, 0, khi, NC, 0, NC, nullptr, nullptr, nullptr);
    gemm_big<256,128,1><<<dim3(128, 1, 1), 256, SM_S>>>(
        wvhi, NC, 0, xnhi, NC, 0, vThi, (long)NB * NT, 0, NC, nullptr, nullptr, nullptr);
    // 6) S = Q K^T (fp16 out)  <- ncu 6th launch
    gemm_big<256,128,1><<<dim3(32, 16, NB), 256, SM_S>>>(
        qhi, NC, (long)NT * NC, khi, NC, (long)NT * NC,
        s16, NT, (long)NT * NT, NC, nullptr, nullptr, nullptr);
    // 7) attn mix (fp16 in/out)
    mix_kernel<<<dim3(NT, NB), 256>>>(w1, w2, s16, ahi);
    // 8) O = attn @ V + residual + transpose -> out[b,c,n]
    gemm_big<128,256,2><<<dim3(1, 32, NB), 256, SM_O>>>(
        ahi, NT, (long)NT * NT, vThi, (long)NB * NT, NT,
        nullptr, 0, 0, NT, xnhi, xnlo, out);
}

// round 17
// speedup vs baseline: 1.0728x; 1.0728x over previous
#include <cuda_runtime.h>
#include <cuda_fp16.h>
#include <math.h>
#include <stdint.h>

#define NB 4
#define NC 256
#define NT 4096

typedef __half h16;

__device__ h16 g_xnhi[NB * NT * NC];
__device__ h16 g_xnlo[NB * NT * NC];
__device__ h16 g_qhi [NB * NT * NC];
__device__ h16 g_khi [NB * NT * NC];
__device__ h16 g_vThi[NC * NB * NT];
__device__ h16 g_s16 [(size_t)NB * NT * NT];
__device__ h16 g_wqhi[NC * NC];
__device__ h16 g_wkhi[NC * NC];
__device__ h16 g_wvhi[NC * NC];

__device__ __forceinline__ uint32_t smem_u32(const void* p) {
    uint32_t a;
    asm("{ .reg .u64 t; cvta.to.shared.u64 t, %1; cvt.u32.u64 %0, t; }" : "=r"(a) : "l"(p));
    return a;
}
__device__ __forceinline__ void cp16(uint32_t s, const void* g) {
    asm volatile("cp.async.cg.shared.global [%0], [%1], 16;" :: "r"(s), "l"(g));
}
__device__ __forceinline__ void cp_commit() { asm volatile("cp.async.commit_group;" ::: "memory"); }
template <int N> __device__ __forceinline__ void cp_wait() {
    asm volatile("cp.async.wait_group %0;" :: "n"(N) : "memory");
}
__device__ __forceinline__ void ldm_x4(uint32_t* r, uint32_t addr) {
    asm volatile("ldmatrix.sync.aligned.m8n8.x4.shared.b16 {%0,%1,%2,%3}, [%4];"
                 : "=r"(r[0]), "=r"(r[1]), "=r"(r[2]), "=r"(r[3]) : "r"(addr));
}
__device__ __forceinline__ void mma16816(float* d, const uint32_t* a, const uint32_t* b) {
    asm volatile(
        "mma.sync.aligned.m16n8k16.row.col.f32.f16.f16.f32 "
        "{%0,%1,%2,%3}, {%4,%5,%6,%7}, {%8,%9}, {%0,%1,%2,%3};"
        : "+f"(d[0]), "+f"(d[1]), "+f"(d[2]), "+f"(d[3])
        : "r"(a[0]), "r"(a[1]), "r"(a[2]), "r"(a[3]), "r"(b[0]), "r"(b[1]));
}
__device__ __forceinline__ uint32_t swz(uint32_t off) { return off ^ ((off >> 3) & 0x70); }
__device__ __forceinline__ uint32_t pack2h(float a, float b) {
    return (uint32_t)__half_as_ushort(__float2half_rn(a))
         | ((uint32_t)__half_as_ushort(__float2half_rn(b)) << 16);
}

// ============================================================
// pure-fp16 GEMM (R15 champion): BK=64, BM=BN=128, 3 stages x 32KB,
// 256 thr (8 warps 2x4), warp tile 64x32, 2 CTA/SM, fp16 out.
// QK=1: blockIdx.z selects B matrix (Bq / Bk) and output (Cq / Ck).
// ============================================================
template <int QK>
__global__ void __launch_bounds__(256, 2) mma_gemm(
    const h16* __restrict__ A, long ldA, long strideA,
    const h16* __restrict__ B, long ldB, long strideB,
    h16* __restrict__ C, long ldC, long strideC, int K,
    const h16* __restrict__ B2, h16* __restrict__ C2)
{
    extern __shared__ char dyn[];
    const uint32_t sbase = smem_u32(dyn);
    const int tid = threadIdx.x;
    const int wid = tid >> 5, lane = tid & 31;
    const int warpM = wid & 1, warpN = wid >> 1;

    constexpr uint32_t PLANE = 16384, STAGE = 32768;

    const int z = blockIdx.z;
    const long m0 = (long)blockIdx.y * 128;
    const long n0 = (long)blockIdx.x * 128;
    const h16* Bm = (QK && z) ? B2 : B;
    h16*       Cm = (QK && z) ? C2 : C;
    const int  zz = QK ? 0 : z;
    const h16* pA = A + (size_t)zz * strideA + (size_t)m0 * ldA;
    const h16* pB = Bm + (size_t)zz * strideB + (size_t)n0 * ldB;

    const int nk = K / 64;

    auto load_stage = [&](int st, int ks) {
        uint32_t base = sbase + (uint32_t)st * STAGE;
#pragma unroll
        for (int i = 0; i < 4; i++) {
            int cid = tid + i * 256;
            int m = cid >> 3, c = cid & 7;
            uint32_t off = swz((uint32_t)(m * 128 + c * 16));
            cp16(base + off,         pA + (size_t)m * ldA + ks * 64 + c * 8);
            cp16(base + PLANE + off, pB + (size_t)m * ldB + ks * 64 + c * 8);
        }
    };

    const int lr = lane & 7, lg = lane >> 3;
    float acc[4][4][4] = {};
    load_stage(0, 0); cp_commit();
    if (nk > 1) { load_stage(1, 1); cp_commit(); }

    for (int ks = 0; ks < nk; ks++) {
        if (ks + 1 < nk) cp_wait<1>(); else cp_wait<0>();
        __syncthreads();
        if (ks + 2 < nk) { load_stage((ks + 2) % 3, ks + 2); cp_commit(); }

        uint32_t aBase = sbase + (uint32_t)(ks % 3) * STAGE;
        uint32_t bBase = aBase + PLANE;

#pragma unroll
        for (int kst = 0; kst < 4; kst++) {
            const uint32_t kb = kst * 32;
            uint32_t ah[4][4], bh[4][2];
#pragma unroll
            for (int mf = 0; mf < 4; mf++) {
                uint32_t row = warpM * 64 + mf * 16 + lr + ((lg & 1) << 3);
                ldm_x4(ah[mf], aBase + swz(row * 128 + kb + ((lg >> 1) << 4)));
            }
#pragma unroll
            for (int p = 0; p < 2; p++) {
                uint32_t row = warpN * 32 + p * 16 + lr + ((lg >> 1) << 3);
                uint32_t t[4];
                ldm_x4(t, bBase + swz(row * 128 + kb + ((lg & 1) << 4)));
                bh[2*p][0] = t[0]; bh[2*p][1] = t[1];
                bh[2*p+1][0] = t[2]; bh[2*p+1][1] = t[3];
            }
#pragma unroll
            for (int mf = 0; mf < 4; mf++)
#pragma unroll
                for (int nf = 0; nf < 4; nf++)
                    mma16816(acc[mf][nf], ah[mf], bh[nf]);
        }
    }

    const int qr = lane >> 2, qc = (lane & 3) * 2;
#pragma unroll
    for (int mf = 0; mf < 4; mf++)
#pragma unroll
        for (int nf = 0; nf < 4; nf++) {
            long r0  = m0 + warpM * 64 + mf * 16 + qr;
            long col = n0 + warpN * 32 + nf * 8 + qc;
#pragma unroll
            for (int h = 0; h < 2; h++) {
                size_t idx = (size_t)zz * strideC + (size_t)(r0 + h * 8) * ldC + col;
                *(uint32_t*)(Cm + idx) = pack2h(acc[mf][nf][2*h], acc[mf][nf][2*h+1]);
            }
        }
}

// ============================================================
// O-GEMM (R15): BM=64, BN=256 (full C), BK=64, 2 stages x 40KB.
// out[b,c,n] = (attn @ V)[n,c] + xn[n,c]. 256 thr, warp tile 32x64.
// ============================================================
__global__ void __launch_bounds__(256, 2) mma_o_gemm(
    const h16* __restrict__ A, const h16* __restrict__ Bv,
    const h16* __restrict__ Rhi, const h16* __restrict__ Rlo,
    float* __restrict__ out)
{
    extern __shared__ char dyn[];
    const uint32_t sbase = smem_u32(dyn);
    const int tid = threadIdx.x;
    const int wid = tid >> 5, lane = tid & 31;
    const int warpM = wid & 1, warpN = wid >> 1;

    constexpr uint32_t APLANE = 8192;
    constexpr uint32_t STAGE  = 8192 + 32768;

    const int z = blockIdx.z;
    const long m0 = (long)blockIdx.y * 64;
    const h16* pA = A + (size_t)z * NT * NT + (size_t)m0 * NT;
    const h16* pB = Bv + (size_t)z * NT;

    const int nk = NT / 64;

    auto load_stage = [&](int st, int ks) {
        uint32_t base = sbase + (uint32_t)st * STAGE;
#pragma unroll
        for (int i = 0; i < 10; i++) {
            int cid = tid + i * 256;
            if (cid < 512) {
                int m = cid >> 3, c = cid & 7;
                uint32_t off = swz((uint32_t)(m * 128 + c * 16));
                cp16(base + off, pA + (size_t)m * NT + ks * 64 + c * 8);
            } else {
                int b = cid - 512;
                int m = b >> 3, c = b & 7;
                uint32_t off = swz((uint32_t)(m * 128 + c * 16));
                cp16(base + APLANE + off, pB + (size_t)m * (NB * NT) + ks * 64 + c * 8);
            }
        }
    };

    const int lr = lane & 7, lg = lane >> 3;
    float acc[2][8][4] = {};
    load_stage(0, 0); cp_commit();

    for (int ks = 0; ks < nk; ks++) {
        cp_wait<0>();
        __syncthreads();
        if (ks + 1 < nk) { load_stage((ks + 1) & 1, ks + 1); cp_commit(); }

        uint32_t aBase = sbase + (uint32_t)(ks & 1) * STAGE;
        uint32_t bBase = aBase + APLANE;

#pragma unroll
        for (int kst = 0; kst < 4; kst++) {
            const uint32_t kb = kst * 32;
            uint32_t ah[2][4], bh[8][2];
#pragma unroll
            for (int mf = 0; mf < 2; mf++) {
                uint32_t row = warpM * 32 + mf * 16 + lr + ((lg & 1) << 3);
                ldm_x4(ah[mf], aBase + swz(row * 128 + kb + ((lg >> 1) << 4)));
            }
#pragma unroll
            for (int p = 0; p < 4; p++) {
                uint32_t row = warpN * 64 + p * 16 + lr + ((lg >> 1) << 3);
                uint32_t t[4];
                ldm_x4(t, bBase + swz(row * 128 + kb + ((lg & 1) << 4)));
                bh[2*p][0] = t[0]; bh[2*p][1] = t[1];
                bh[2*p+1][0] = t[2]; bh[2*p+1][1] = t[3];
            }
#pragma unroll
            for (int mf = 0; mf < 2; mf++)
#pragma unroll
                for (int nf = 0; nf < 8; nf++)
                    mma16816(acc[mf][nf], ah[mf], bh[nf]);
        }
    }

    const int qr = lane >> 2, qc = (lane & 3) * 2;
    __syncthreads();
    float* tr = (float*)dyn;                    // [256][68]
#pragma unroll
    for (int mf = 0; mf < 2; mf++)
#pragma unroll
        for (int nf = 0; nf < 8; nf++) {
            int row_l = warpM * 32 + mf * 16 + qr;
            int col_l = warpN * 64 + nf * 8 + qc;
#pragma unroll
            for (int h = 0; h < 2; h++) {
                size_t idx = ((size_t)z * NT + m0 + row_l + h * 8) * NC + col_l;
                uint32_t xh = *(const uint32_t*)(Rhi + idx);
                uint32_t xl = *(const uint32_t*)(Rlo + idx);
                float r0v = __half2float(__ushort_as_half((unsigned short)(xh & 0xffff)))
                          + __half2float(__ushort_as_half((unsigned short)(xl & 0xffff)));
                float r1v = __half2float(__ushort_as_half((unsigned short)(xh >> 16)))
                          + __half2float(__ushort_as_half((unsigned short)(xl >> 16)));
                tr[(col_l)     * 68 + row_l + h * 8] = acc[mf][nf][2*h]     + r0v;
                tr[(col_l + 1) * 68 + row_l + h * 8] = acc[mf][nf][2*h + 1] + r1v;
            }
        }
    __syncthreads();
#pragma unroll
    for (int it = 0; it < 16; it++) {
        int col = (tid >> 4) + it * 16;
        int t4  = (tid & 15) * 4;
        float4 v = *(float4*)&tr[col * 68 + t4];
        *(float4*)(out + ((size_t)z * NC + col) * NT + m0 + t4) = v;
    }
}

// ============================================================
__global__ void __launch_bounds__(256) ln_kernel(
    const float* __restrict__ x, const float* __restrict__ gamma,
    const float* __restrict__ beta, h16* __restrict__ xnhi, h16* __restrict__ xnlo)
{
    __shared__ float sx[32][NC + 1];
    __shared__ float psum[8][33], psq[8][33];
    __shared__ float smu[32], srs[32];
    int b = blockIdx.y, n0 = blockIdx.x * 32;
    const float* xb = x + (size_t)b * NC * NT;

    for (int i = threadIdx.x; i < NC * 32; i += 256) {
        int c = i >> 5, t = i & 31;
        sx[t][c] = xb[(size_t)c * NT + n0 + t];
    }
    __syncthreads();
    int t = threadIdx.x & 31, g = threadIdx.x >> 5;
    float s0 = 0.f, s1 = 0.f;
#pragma unroll
    for (int j = 0; j < 32; j++) { float v = sx[t][g * 32 + j]; s0 += v; s1 += v * v; }
    psum[g][t] = s0; psq[g][t] = s1;
    __syncthreads();
    if (threadIdx.x < 32) {
        float a = 0.f, bb = 0.f;
#pragma unroll
        for (int j = 0; j < 8; j++) { a += psum[j][threadIdx.x]; bb += psq[j][threadIdx.x]; }
        float mu = a * (1.0f / NC);
        smu[threadIdx.x] = mu;
        srs[threadIdx.x] = rsqrtf(bb * (1.0f / NC) - mu * mu + 1e-5f);
    }
    __syncthreads();
    size_t base = ((size_t)b * NT + n0) * NC;
    for (int i = threadIdx.x; i < NC * 32; i += 256) {
        int tok = i >> 8, c = i & 255;
        float r = (sx[tok][c] - smu[tok]) * srs[tok] * gamma[c] + beta[c];
        float h = __half2float(__float2half_rn(r));
        xnhi[base + (size_t)tok * NC + c] = __float2half_rn(r);
        xnlo[base + (size_t)tok * NC + c] = __float2half_rn(r - h);
    }
}

__global__ void prep_kernel(
    const float* __restrict__ Wq, const float* __restrict__ Wk, const float* __restrict__ Wv,
    h16* qh, h16* kh, h16* vh)
{
    int n = blockIdx.x, k = threadIdx.x;
    size_t src = (size_t)k * NC + n, dst = (size_t)n * NC + k;
    qh[dst] = __float2half_rn(Wq[src]);
    kh[dst] = __float2half_rn(Wk[src]);
    vh[dst] = __float2half_rn(Wv[src]);
}

// mix: attn = a1*softmax + a2*relu^2, fp16, IN-PLACE on S
__global__ void __launch_bounds__(256) mix_kernel(
    const float* __restrict__ w1, const float* __restrict__ w2,
    h16* __restrict__ S)
{
    size_t ro = ((size_t)blockIdx.y * NT + blockIdx.x) * NT;
    uint2* row2 = (uint2*)(S + ro);
    int tid = threadIdx.x;
    __shared__ float sred[8];

    float v[16];
    float mx = -1e30f;
#pragma unroll
    for (int g = 0; g < 4; g++) {
        uint2 u = row2[g * 256 + tid];
        v[g*4+0] = __half2float(__ushort_as_half((unsigned short)(u.x & 0xffff)));
        v[g*4+1] = __half2float(__ushort_as_half((unsigned short)(u.x >> 16)));
        v[g*4+2] = __half2float(__ushort_as_half((unsigned short)(u.y & 0xffff)));
        v[g*4+3] = __half2float(__ushort_as_half((unsigned short)(u.y >> 16)));
    }
#pragma unroll
    for (int i = 0; i < 16; i++) mx = fmaxf(mx, v[i]);
#pragma unroll
    for (int o = 16; o; o >>= 1) mx = fmaxf(mx, __shfl_xor_sync(0xffffffffu, mx, o));
    if ((tid & 31) == 0) sred[tid >> 5] = mx;
    __syncthreads();
    mx = sred[0];
#pragma unroll
    for (int i = 1; i < 8; i++) mx = fmaxf(mx, sred[i]);
    __syncthreads();

    float e[16];
    float sum = 0.f;
#pragma unroll
    for (int i = 0; i < 16; i++) { e[i] = __expf(v[i] - mx); sum += e[i]; }
#pragma unroll
    for (int o = 16; o; o >>= 1) sum += __shfl_xor_sync(0xffffffffu, sum, o);
    if ((tid & 31) == 0) sred[tid >> 5] = sum;
    __syncthreads();
    sum = 0.f;
#pragma unroll
    for (int i = 0; i < 8; i++) sum += sred[i];

    float e1 = __expf(w1[0]), e2 = __expf(w2[0]);
    float a1 = e1 / (e1 + e2), a2 = e2 / (e1 + e2);
    float inv = a1 / sum;

#pragma unroll
    for (int g = 0; g < 4; g++) {
        float p[4];
#pragma unroll
        for (int j = 0; j < 4; j++) {
            float r = fmaxf(v[g*4+j], 0.f);
            p[j] = e[g*4+j] * inv + a2 * r * r;
        }
        row2[g * 256 + tid] = make_uint2(pack2h(p[0], p[1]), pack2h(p[2], p[3]));
    }
}

// ============================================================
extern "C" void kernel_launch(void* const* d_in, const int* in_sizes, int n_in,
                              void* d_out, int out_size)
{
    const float* x     = (const float*)d_in[0];
    const float* gamma = (const float*)d_in[1];
    const float* beta  = (const float*)d_in[2];
    const float* Wq    = (const float*)d_in[3];
    const float* Wk    = (const float*)d_in[4];
    const float* Wv    = (const float*)d_in[5];
    const float* w1    = (const float*)d_in[6];
    const float* w2    = (const float*)d_in[7];
    float* out = (float*)d_out;

    h16 *xnhi, *xnlo, *qhi, *khi, *vThi, *wqhi, *wkhi, *wvhi, *s16;
    cudaGetSymbolAddress((void**)&xnhi, g_xnhi); cudaGetSymbolAddress((void**)&xnlo, g_xnlo);
    cudaGetSymbolAddress((void**)&qhi,  g_qhi);
    cudaGetSymbolAddress((void**)&khi,  g_khi);
    cudaGetSymbolAddress((void**)&vThi, g_vThi);
    cudaGetSymbolAddress((void**)&wqhi, g_wqhi);
    cudaGetSymbolAddress((void**)&wkhi, g_wkhi);
    cudaGetSymbolAddress((void**)&wvhi, g_wvhi);
    cudaGetSymbolAddress((void**)&s16,  g_s16);

    cudaFuncSetAttribute((const void*)mma_gemm<0>,  cudaFuncAttributeMaxDynamicSharedMemorySize, 98304);
    cudaFuncSetAttribute((const void*)mma_gemm<1>,  cudaFuncAttributeMaxDynamicSharedMemorySize, 98304);
    cudaFuncSetAttribute((const void*)mma_o_gemm,   cudaFuncAttributeMaxDynamicSharedMemorySize, 98304);

    // 1) LayerNorm -> xn pair
    ln_kernel<<<dim3(NT / 32, NB), 256>>>(x, gamma, beta, xnhi, xnlo);
    // 2) weight transpose
    prep_kernel<<<NC, NC>>>(Wq, Wk, Wv, wqhi, wkhi, wvhi);
    // 3) Q and K projections merged (z=0 -> Q, z=1 -> K)
    mma_gemm<1><<<dim3(2, 128, 2), 256, 98304>>>(
        xnhi, NC, 0, wqhi, NC, 0, qhi, NC, 0, NC, wkhi, khi);
    // 4) V^T projection
    mma_gemm<0><<<dim3(128, 2, 1), 256, 98304>>>(
        wvhi, NC, 0, xnhi, NC, 0, vThi, (long)NB * NT, 0, NC, nullptr, nullptr);
    // 5) S = Q K^T (fp16 out)
    mma_gemm<0><<<dim3(32, 32, NB), 256, 98304>>>(
        qhi, NC, (long)NT * NC, khi, NC, (long)NT * NC,
        s16, NT, (long)NT * NT, NC, nullptr, nullptr);
    // 6) attn mix, in place on s16
    mix_kernel<<<dim3(NT, NB), 256>>>(w1, w2, s16);
    // 7) O = attn @ V + residual + transpose -> out[b,c,n]
    mma_o_gemm<<<dim3(1, 64, NB), 256, 98304>>>(s16, vThi, xnhi, xnlo, out);
}